// round 1
// baseline (speedup 1.0000x reference)
#include <cuda_runtime.h>
#include <math.h>

#define NEGV (-1000000000.0f)
#define FLT_MAXV 3.402823466e38f

// Problem constants
static const int BSZ  = 4096;
static const int HD   = 1024;
static const int AA   = 47;
static const int K0   = 7150;   // S*F
static const int K0P  = 7168;   // padded to /16 and float4-aligned

// Output layout (float32 concat of the 4 outputs)
static const long OFF_LOGITS = 0;                 // 4096*94
static const long OFF_LP     = 385024;            // 4096*2
static const long OFF_ACT    = 393216;            // 4096*2
static const long OFF_VAL    = 401408;            // 4096

// ---------------- scratch (static device globals; no dynamic alloc) -------------
__device__ float g_Xpad[4096 * 7168];   // padded input
__device__ float g_W0pad[7168 * 1024];  // padded W0
__device__ float g_Y[4096 * 1024];      // GEMM output
__device__ float g_X[4096 * 1024];      // LN+ReLU output
__device__ float g_Wh[1024 * 128];      // packed head weights (Wp | Wv | pad)
__device__ float g_bh[128];             // packed head bias
__device__ float g_Yh[4096 * 128];      // head output

// ---------------- prep kernels ----------------
__global__ void pad_obs_k(const float* __restrict__ obs) {
    long idx = (long)blockIdx.x * blockDim.x + threadIdx.x;
    if (idx >= (long)4096 * 7168) return;
    int r = (int)(idx / 7168);
    int c = (int)(idx % 7168);
    g_Xpad[idx] = (c < K0) ? obs[(long)r * K0 + c] : 0.0f;
}

__global__ void pad_w0_k(const float* __restrict__ W0) {
    long idx = (long)blockIdx.x * blockDim.x + threadIdx.x;
    if (idx >= (long)7168 * 1024) return;
    int r = (int)(idx / 1024);
    int c = (int)(idx % 1024);
    g_W0pad[idx] = (r < K0) ? W0[(long)r * 1024 + c] : 0.0f;
}

__global__ void prep_head_k(const float* __restrict__ Wp, const float* __restrict__ bp,
                            const float* __restrict__ Wv, const float* __restrict__ bv) {
    int idx = blockIdx.x * blockDim.x + threadIdx.x;
    if (idx < 1024 * 128) {
        int k = idx / 128;
        int c = idx % 128;
        float v = 0.0f;
        if (c < 94)       v = Wp[k * 94 + c];
        else if (c == 94) v = Wv[k];
        g_Wh[idx] = v;
    }
    if (idx < 128) {
        float v = 0.0f;
        if (idx < 94)       v = bp[idx];
        else if (idx == 94) v = bv[0];
        g_bh[idx] = v;
    }
}

// ---------------- GEMM: C = A(MxK) @ B(KxN) + bias, row-major ----------------
template<int BM, int BN, int BK, int TM, int TN>
__global__ __launch_bounds__(256, 2)
void gemm_bias(const float* __restrict__ A, const float* __restrict__ Bm,
               const float* __restrict__ bias, float* __restrict__ C,
               int M, int N, int K)
{
    __shared__ float As[BK][BM + 4];
    __shared__ float Bs[BK][BN];

    const int tid = threadIdx.x;
    const int NXT = BN / TN;            // threads along N
    const int tx  = tid % NXT;
    const int ty  = tid / NXT;
    const int bm  = blockIdx.y * BM;
    const int bn  = blockIdx.x * BN;

    constexpr int NT = (BM / TM) * (BN / TN);   // 256
    constexpr int nA = (BM * BK) / (NT * 4);
    constexpr int nB = (BN * BK) / (NT * 4);

    float acc[TM][TN];
    #pragma unroll
    for (int m = 0; m < TM; m++)
        #pragma unroll
        for (int n = 0; n < TN; n++) acc[m][n] = 0.0f;

    for (int kt = 0; kt < K; kt += BK) {
        #pragma unroll
        for (int i = 0; i < nA; i++) {
            int lin = (tid + i * NT) * 4;
            int r = lin / BK, c = lin % BK;
            float4 v = *(const float4*)(A + (long)(bm + r) * K + kt + c);
            As[c + 0][r] = v.x;
            As[c + 1][r] = v.y;
            As[c + 2][r] = v.z;
            As[c + 3][r] = v.w;
        }
        #pragma unroll
        for (int i = 0; i < nB; i++) {
            int lin = (tid + i * NT) * 4;
            int r = lin / BN, c = lin % BN;
            *(float4*)&Bs[r][c] = *(const float4*)(Bm + (long)(kt + r) * N + bn + c);
        }
        __syncthreads();

        #pragma unroll
        for (int k = 0; k < BK; k++) {
            float ra[TM], rb[TN];
            #pragma unroll
            for (int m = 0; m < TM; m++) ra[m] = As[k][ty * TM + m];
            #pragma unroll
            for (int n = 0; n < TN; n++) rb[n] = Bs[k][tx * TN + n];
            #pragma unroll
            for (int m = 0; m < TM; m++)
                #pragma unroll
                for (int n = 0; n < TN; n++)
                    acc[m][n] = fmaf(ra[m], rb[n], acc[m][n]);
        }
        __syncthreads();
    }

    #pragma unroll
    for (int m = 0; m < TM; m++) {
        int row = bm + ty * TM + m;
        #pragma unroll
        for (int n = 0; n < TN; n += 4) {
            int col = bn + tx * TN + n;
            float4 o;
            o.x = acc[m][n + 0] + bias[col + 0];
            o.y = acc[m][n + 1] + bias[col + 1];
            o.z = acc[m][n + 2] + bias[col + 2];
            o.w = acc[m][n + 3] + bias[col + 3];
            *(float4*)(C + (long)row * N + col) = o;
        }
    }
}

// ---------------- fused LayerNorm + ReLU (1 block per row, H=1024) -------------
__global__ void ln_relu_k(const float* __restrict__ Y, const float* __restrict__ g,
                          const float* __restrict__ be, float* __restrict__ X)
{
    const int row = blockIdx.x;
    const int tid = threadIdx.x;          // 256 threads, 4 floats each
    float4 v = ((const float4*)(Y + (long)row * 1024))[tid];

    float s  = v.x + v.y + v.z + v.w;
    float sq = v.x * v.x + v.y * v.y + v.z * v.z + v.w * v.w;

    __shared__ float ss[8], qq[8];
    #pragma unroll
    for (int off = 16; off; off >>= 1) {
        s  += __shfl_xor_sync(0xffffffffu, s,  off);
        sq += __shfl_xor_sync(0xffffffffu, sq, off);
    }
    int w = tid >> 5, l = tid & 31;
    if (l == 0) { ss[w] = s; qq[w] = sq; }
    __syncthreads();

    __shared__ float smean, srstd;
    if (tid < 32) {
        float s2 = (tid < 8) ? ss[tid] : 0.0f;
        float q2 = (tid < 8) ? qq[tid] : 0.0f;
        #pragma unroll
        for (int off = 4; off; off >>= 1) {
            s2 += __shfl_xor_sync(0xffffffffu, s2, off);
            q2 += __shfl_xor_sync(0xffffffffu, q2, off);
        }
        if (tid == 0) {
            float m   = s2 * (1.0f / 1024.0f);
            float var = q2 * (1.0f / 1024.0f) - m * m;
            smean = m;
            srstd = rsqrtf(var + 1e-5f);
        }
    }
    __syncthreads();
    float m = smean, r = srstd;

    float4 gv = ((const float4*)g)[tid];
    float4 bv = ((const float4*)be)[tid];
    float4 o;
    o.x = fmaxf(0.0f, (v.x - m) * r * gv.x + bv.x);
    o.y = fmaxf(0.0f, (v.y - m) * r * gv.y + bv.y);
    o.z = fmaxf(0.0f, (v.z - m) * r * gv.z + bv.z);
    o.w = fmaxf(0.0f, (v.w - m) * r * gv.w + bv.w);
    ((float4*)(X + (long)row * 1024))[tid] = o;
}

// ---------------- sampling: 1 warp per batch row --------------------------------
__global__ void sample_k(const float* __restrict__ Yh, const int* __restrict__ mask,
                         const float* __restrict__ gum, float* __restrict__ out)
{
    const int warp = threadIdx.x >> 5;
    const int lane = threadIdx.x & 31;
    const int b    = blockIdx.x * 4 + warp;
    const float* lr = Yh + (long)b * 128;

    // copy raw logits + value
    for (int a = lane; a < 94; a += 32)
        out[OFF_LOGITS + (long)b * 94 + a] = lr[a];
    if (lane == 0)
        out[OFF_VAL + b] = lr[94];

    int a_prev = -1;
    #pragma unroll
    for (int j = 0; j < 2; j++) {
        int mk[2];
        #pragma unroll
        for (int t = 0; t < 2; t++) {
            int a = lane + 32 * t;
            int m = 0;
            if (a < AA) {
                m = mask[(long)b * 94 + j * 47 + a];
                if (j == 1) {
                    if (a_prev >= 1 && a_prev <= 6 && a == a_prev) m = 0;
                    if (a_prev > 26 && a_prev <= 46 && a >= 27)    m = 0;
                    if (a_prev == 0 && a == 0)                     m = 0;
                }
            }
            mk[t] = m;
        }
        if (j == 1) {
            int ssum = mk[0] + mk[1];
            #pragma unroll
            for (int off = 16; off; off >>= 1)
                ssum += __shfl_xor_sync(0xffffffffu, ssum, off);
            if (ssum == 0 && a_prev == 0 && lane == 0) mk[0] = 1;
        }

        float lv[2], key[2];
        #pragma unroll
        for (int t = 0; t < 2; t++) {
            int a = lane + 32 * t;
            if (a < AA) {
                float lg = lr[j * 47 + a];
                lv[t]  = mk[t] ? lg : NEGV;
                key[t] = lv[t] + gum[(long)b * 94 + j * 47 + a];
            } else {
                lv[t]  = -FLT_MAXV;
                key[t] = -FLT_MAXV;
            }
        }

        // argmax of key, first-index tie break
        float bk = key[0]; int bi = lane;
        if (key[1] > bk) { bk = key[1]; bi = lane + 32; }
        #pragma unroll
        for (int off = 16; off; off >>= 1) {
            float ok = __shfl_xor_sync(0xffffffffu, bk, off);
            int   oi = __shfl_xor_sync(0xffffffffu, bi, off);
            if (ok > bk || (ok == bk && oi < bi)) { bk = ok; bi = oi; }
        }

        // log_softmax at bi
        float mx = fmaxf(lv[0], lv[1]);
        #pragma unroll
        for (int off = 16; off; off >>= 1)
            mx = fmaxf(mx, __shfl_xor_sync(0xffffffffu, mx, off));
        float es = 0.0f;
        if (lane      < AA) es += expf(lv[0] - mx);
        if (lane + 32 < AA) es += expf(lv[1] - mx);
        #pragma unroll
        for (int off = 16; off; off >>= 1)
            es += __shfl_xor_sync(0xffffffffu, es, off);

        float lsel = __shfl_sync(0xffffffffu, lv[bi >= 32 ? 1 : 0], bi & 31);
        float logp = lsel - mx - logf(es);

        if (lane == 0) {
            out[OFF_LP  + (long)b * 2 + j] = logp;
            out[OFF_ACT + (long)b * 2 + j] = (float)bi;
        }
        a_prev = bi;
    }
}

// ---------------- launcher ----------------
extern "C" void kernel_launch(void* const* d_in, const int* in_sizes, int n_in,
                              void* d_out, int out_size)
{
    const float* obs  = (const float*)d_in[0];
    const int*   am   = (const int*)  d_in[1];
    const float* gum  = (const float*)d_in[2];
    const float* W0   = (const float*)d_in[3];
    const float* b0   = (const float*)d_in[4];
    const float* g0   = (const float*)d_in[5];
    const float* be0  = (const float*)d_in[6];
    const float* W1   = (const float*)d_in[7];
    const float* b1   = (const float*)d_in[8];
    const float* g1   = (const float*)d_in[9];
    const float* be1  = (const float*)d_in[10];
    const float* W2   = (const float*)d_in[11];
    const float* b2   = (const float*)d_in[12];
    const float* g2   = (const float*)d_in[13];
    const float* be2  = (const float*)d_in[14];
    const float* Wp   = (const float*)d_in[15];
    const float* bp   = (const float*)d_in[16];
    const float* Wv   = (const float*)d_in[17];
    const float* bv   = (const float*)d_in[18];
    float* out = (float*)d_out;

    // resolve scratch symbols (host API, not a stream op; capture-safe)
    float *Xpad, *W0pad, *Y, *X, *Wh, *bh, *Yh;
    cudaGetSymbolAddress((void**)&Xpad,  g_Xpad);
    cudaGetSymbolAddress((void**)&W0pad, g_W0pad);
    cudaGetSymbolAddress((void**)&Y,     g_Y);
    cudaGetSymbolAddress((void**)&X,     g_X);
    cudaGetSymbolAddress((void**)&Wh,    g_Wh);
    cudaGetSymbolAddress((void**)&bh,    g_bh);
    cudaGetSymbolAddress((void**)&Yh,    g_Yh);

    // prep / padding
    {
        long n = (long)4096 * 7168;
        pad_obs_k<<<(unsigned)((n + 255) / 256), 256>>>(obs);
    }
    {
        long n = (long)7168 * 1024;
        pad_w0_k<<<(unsigned)((n + 255) / 256), 256>>>(W0);
    }
    prep_head_k<<<(1024 * 128 + 255) / 256, 256>>>(Wp, bp, Wv, bv);

    dim3 grid_big(1024 / 128, 4096 / 128);   // (8, 32)

    // layer 0
    gemm_bias<128, 128, 16, 8, 8><<<grid_big, 256>>>(Xpad, W0pad, b0, Y, 4096, 1024, 7168);
    ln_relu_k<<<4096, 256>>>(Y, g0, be0, X);
    // layer 1
    gemm_bias<128, 128, 16, 8, 8><<<grid_big, 256>>>(X, W1, b1, Y, 4096, 1024, 1024);
    ln_relu_k<<<4096, 256>>>(Y, g1, be1, X);
    // layer 2
    gemm_bias<128, 128, 16, 8, 8><<<grid_big, 256>>>(X, W2, b2, Y, 4096, 1024, 1024);
    ln_relu_k<<<4096, 256>>>(Y, g2, be2, X);

    // heads (N padded to 128: cols 0..93 = policy, 94 = value)
    gemm_bias<64, 128, 16, 4, 8><<<dim3(1, 4096 / 64), 256>>>(X, Wh, bh, Yh, 4096, 128, 1024);

    // sampling + output packing
    sample_k<<<4096 / 4, 128>>>(Yh, am, gum, out);
}

// round 3
// speedup vs baseline: 2.4691x; 2.4691x over previous
#include <cuda_runtime.h>
#include <cuda_bf16.h>
#include <cstdint>
#include <math.h>

#define NEGV (-1000000000.0f)
#define FLT_MAXV 3.402823466e38f

// ---------------- output layout ----------------
static const long OFF_LOGITS = 0;
static const long OFF_LP     = 385024;
static const long OFF_ACT    = 393216;
static const long OFF_VAL    = 401408;

#define SWZ128(x) ((x) ^ (((x) >> 3) & 0x70))

__device__ __forceinline__ uint32_t smem_to_u32(const void* p) {
    uint32_t a;
    asm("{ .reg .u64 t; cvta.to.shared.u64 t, %1; cvt.u32.u64 %0, t; }" : "=r"(a) : "l"(p));
    return a;
}
__device__ __forceinline__ void cp16(uint32_t sad, const void* gad) {
    asm volatile("cp.async.cg.shared.global [%0], [%1], 16;" :: "r"(sad), "l"(gad) : "memory");
}
__device__ __forceinline__ void ldm_x4(uint32_t* r, uint32_t addr) {
    asm volatile("ldmatrix.sync.aligned.m8n8.x4.shared.b16 {%0,%1,%2,%3}, [%4];"
                 : "=r"(r[0]), "=r"(r[1]), "=r"(r[2]), "=r"(r[3]) : "r"(addr));
}
__device__ __forceinline__ void mma16816(float* c, const uint32_t* a, const uint32_t* b) {
    asm volatile("mma.sync.aligned.m16n8k16.row.col.f32.bf16.bf16.f32 "
                 "{%0,%1,%2,%3}, {%4,%5,%6,%7}, {%8,%9}, {%0,%1,%2,%3};"
                 : "+f"(c[0]), "+f"(c[1]), "+f"(c[2]), "+f"(c[3])
                 : "r"(a[0]), "r"(a[1]), "r"(a[2]), "r"(a[3]), "r"(b[0]), "r"(b[1]));
}

// ---------------- scratch (device globals) ----------------
__device__ __nv_bfloat16 g_A0h[4096L * 7168];
__device__ __nv_bfloat16 g_A0l[4096L * 7168];
__device__ __nv_bfloat16 g_B0h[1024L * 7168];
__device__ __nv_bfloat16 g_B0l[1024L * 7168];
__device__ __nv_bfloat16 g_B1h[1024L * 1024];
__device__ __nv_bfloat16 g_B1l[1024L * 1024];
__device__ __nv_bfloat16 g_B2h[1024L * 1024];
__device__ __nv_bfloat16 g_B2l[1024L * 1024];
__device__ __nv_bfloat16 g_Bhh[128L * 1024];
__device__ __nv_bfloat16 g_Bhl[128L * 1024];
__device__ float         g_bh[128];
__device__ float         g_Y[4096L * 1024];
__device__ __nv_bfloat16 g_Xh[4096L * 1024];
__device__ __nv_bfloat16 g_Xl[4096L * 1024];
__device__ float         g_Yh[4096L * 128];

// ---------------- conversion kernels ----------------
__global__ void split_obs_k(const float* __restrict__ obs) {
    long idx = (long)blockIdx.x * blockDim.x + threadIdx.x;
    if (idx >= 4096L * 7168) return;
    int r = (int)(idx / 7168);
    int c = (int)(idx % 7168);
    float x = (c < 7150) ? obs[(long)r * 7150 + c] : 0.0f;
    __nv_bfloat16 h = __float2bfloat16(x);
    g_A0h[idx] = h;
    g_A0l[idx] = __float2bfloat16(x - __bfloat162float(h));
}

// W (K x N fp32) -> Bt hi/lo (N x Kpad bf16), transposed + split
__global__ void transpose_split_k(const float* __restrict__ W,
                                  __nv_bfloat16* __restrict__ Bh,
                                  __nv_bfloat16* __restrict__ Bl,
                                  int K, int Kpad, int N) {
    __shared__ float t[32][33];
    int k0 = blockIdx.x * 32, n0 = blockIdx.y * 32;
    int tx = threadIdx.x, ty = threadIdx.y;   // (32, 8)
    #pragma unroll
    for (int d = 0; d < 4; d++) {
        int k = k0 + ty + d * 8;
        t[ty + d * 8][tx] = (k < K) ? W[(size_t)k * N + n0 + tx] : 0.0f;
    }
    __syncthreads();
    #pragma unroll
    for (int d = 0; d < 4; d++) {
        int n = n0 + ty + d * 8;
        int k = k0 + tx;
        float x = t[tx][ty + d * 8];
        __nv_bfloat16 h = __float2bfloat16(x);
        Bh[(size_t)n * Kpad + k] = h;
        Bl[(size_t)n * Kpad + k] = __float2bfloat16(x - __bfloat162float(h));
    }
}

__global__ void pack_head_k(const float* __restrict__ Wp, const float* __restrict__ bp,
                            const float* __restrict__ Wv, const float* __restrict__ bv) {
    int idx = blockIdx.x * blockDim.x + threadIdx.x;
    if (idx < 128 * 1024) {
        int n = idx / 1024;
        int k = idx % 1024;
        float x = 0.0f;
        if (n < 94)       x = Wp[(size_t)k * 94 + n];
        else if (n == 94) x = Wv[k];
        __nv_bfloat16 h = __float2bfloat16(x);
        g_Bhh[idx] = h;
        g_Bhl[idx] = __float2bfloat16(x - __bfloat162float(h));
    }
    if (idx < 128) {
        float v = 0.0f;
        if (idx < 94)       v = bp[idx];
        else if (idx == 94) v = bv[0];
        g_bh[idx] = v;
    }
}

// ---------------- HMMA GEMM: C(MxN) = A(MxK) @ Bt(NxK)^T + bias ----------------
// 3-way bf16 split in one K loop: Ahi@Bhi + Alo@Bhi + Ahi@Blo.
// CTA: 128x128x64, 3-stage cp.async pipeline, SW128 smem, ldmatrix + mma.m16n8k16.
__global__ void __launch_bounds__(256, 2)
gemm_hmma(const __nv_bfloat16* __restrict__ Ahi, const __nv_bfloat16* __restrict__ Alo,
          const __nv_bfloat16* __restrict__ Bhi, const __nv_bfloat16* __restrict__ Blo,
          const float* __restrict__ bias, float* __restrict__ C, int N, int K)
{
    extern __shared__ char smem[];
    const uint32_t sbase = smem_to_u32(smem);
    const int tid  = threadIdx.x;
    const int wid  = tid >> 5;
    const int lane = tid & 31;
    const int bm   = blockIdx.y * 128;
    const int bn   = blockIdx.x * 128;
    const int wm   = (wid >> 2) * 64;   // warp M offset: 0 / 64
    const int wn   = (wid & 3) * 32;    // warp N offset: 0/32/64/96

    const int nk    = K >> 6;           // 64-wide K tiles per segment
    const int niter = 3 * nk;

    float acc[4][4][4];
    #pragma unroll
    for (int im = 0; im < 4; im++)
        #pragma unroll
        for (int in = 0; in < 4; in++)
            #pragma unroll
            for (int j = 0; j < 4; j++) acc[im][in][j] = 0.0f;

    // stage loader: A tile 128x128B at so, B tile 128x128B at so+16384
    auto load_stage = [&](int t) {
        int seg = t >= 2 * nk ? 2 : (t >= nk ? 1 : 0);
        int kk  = (t - seg * nk) << 6;
        const __nv_bfloat16* Ap = (seg == 1) ? Alo : Ahi;
        const __nv_bfloat16* Bp = (seg == 2) ? Blo : Bhi;
        uint32_t so = (uint32_t)(t % 3) * 32768u;
        #pragma unroll
        for (int j = 0; j < 4; j++) {
            int ch  = tid + j * 256;
            int row = ch >> 3;
            int cb  = (ch & 7) << 4;
            cp16(sbase + so + SWZ128((uint32_t)(row * 128 + cb)),
                 Ap + (size_t)(bm + row) * K + kk + ((ch & 7) << 3));
        }
        #pragma unroll
        for (int j = 0; j < 4; j++) {
            int ch  = tid + j * 256;
            int row = ch >> 3;
            int cb  = (ch & 7) << 4;
            cp16(sbase + so + 16384u + SWZ128((uint32_t)(row * 128 + cb)),
                 Bp + (size_t)(bn + row) * K + kk + ((ch & 7) << 3));
        }
    };

    // prologue: stages 0, 1
    load_stage(0);
    asm volatile("cp.async.commit_group;" ::: "memory");
    load_stage(1);
    asm volatile("cp.async.commit_group;" ::: "memory");

    for (int t = 0; t < niter; t++) {
        asm volatile("cp.async.wait_group 1;" ::: "memory");
        __syncthreads();

        if (t + 2 < niter) load_stage(t + 2);
        asm volatile("cp.async.commit_group;" ::: "memory");

        uint32_t sa = sbase + (uint32_t)(t % 3) * 32768u;
        uint32_t sb = sa + 16384u;

        #pragma unroll
        for (int ks = 0; ks < 4; ks++) {
            // A fragments: 4 x m16k16
            uint32_t a[4][4];
            {
                int arow = wm + (lane & 15);
                int akb  = ks * 32 + ((lane >> 4) << 4);
                #pragma unroll
                for (int im = 0; im < 4; im++)
                    ldm_x4(a[im], sa + SWZ128((uint32_t)(((arow + im * 16) << 7) + akb)));
            }
            // B fragments: 2 x (two n8k16 frags each)
            uint32_t b[2][4];
            {
                int brow = wn + (lane & 7) + ((lane >> 4) << 3);
                int bkb  = ks * 32 + (((lane >> 3) & 1) << 4);
                #pragma unroll
                for (int ib = 0; ib < 2; ib++)
                    ldm_x4(b[ib], sb + SWZ128((uint32_t)(((brow + ib * 16) << 7) + bkb)));
            }
            #pragma unroll
            for (int im = 0; im < 4; im++)
                #pragma unroll
                for (int in = 0; in < 4; in++)
                    mma16816(acc[im][in], a[im], &b[in >> 1][(in & 1) * 2]);
        }
    }

    // epilogue: bias + direct stores (fragment-native layout)
    #pragma unroll
    for (int in = 0; in < 4; in++) {
        int col = bn + wn + in * 8 + ((lane & 3) << 1);
        float bx = bias[col], by = bias[col + 1];
        #pragma unroll
        for (int im = 0; im < 4; im++) {
            int row = bm + wm + im * 16 + (lane >> 2);
            float2 v0 = { acc[im][in][0] + bx, acc[im][in][1] + by };
            float2 v1 = { acc[im][in][2] + bx, acc[im][in][3] + by };
            *(float2*)(C + (size_t)row * N + col)       = v0;
            *(float2*)(C + (size_t)(row + 8) * N + col) = v1;
        }
    }
}

// ---------------- fused LayerNorm + ReLU + bf16 split -------------
__global__ void ln_relu_split_k(const float* __restrict__ Y, const float* __restrict__ g,
                                const float* __restrict__ be,
                                __nv_bfloat16* __restrict__ Xh, __nv_bfloat16* __restrict__ Xl)
{
    const int row = blockIdx.x;
    const int tid = threadIdx.x;          // 256 threads, 4 floats each
    float4 v = ((const float4*)(Y + (long)row * 1024))[tid];

    float s  = v.x + v.y + v.z + v.w;
    float sq = v.x * v.x + v.y * v.y + v.z * v.z + v.w * v.w;

    __shared__ float ss[8], qq[8];
    #pragma unroll
    for (int off = 16; off; off >>= 1) {
        s  += __shfl_xor_sync(0xffffffffu, s,  off);
        sq += __shfl_xor_sync(0xffffffffu, sq, off);
    }
    int w = tid >> 5, l = tid & 31;
    if (l == 0) { ss[w] = s; qq[w] = sq; }
    __syncthreads();

    __shared__ float smean, srstd;
    if (tid < 32) {
        float s2 = (tid < 8) ? ss[tid] : 0.0f;
        float q2 = (tid < 8) ? qq[tid] : 0.0f;
        #pragma unroll
        for (int off = 4; off; off >>= 1) {
            s2 += __shfl_xor_sync(0xffffffffu, s2, off);
            q2 += __shfl_xor_sync(0xffffffffu, q2, off);
        }
        if (tid == 0) {
            float m   = s2 * (1.0f / 1024.0f);
            float var = q2 * (1.0f / 1024.0f) - m * m;
            smean = m;
            srstd = rsqrtf(var + 1e-5f);
        }
    }
    __syncthreads();
    float m = smean, r = srstd;

    float4 gv = ((const float4*)g)[tid];
    float4 bv = ((const float4*)be)[tid];
    float o[4];
    o[0] = fmaxf(0.0f, (v.x - m) * r * gv.x + bv.x);
    o[1] = fmaxf(0.0f, (v.y - m) * r * gv.y + bv.y);
    o[2] = fmaxf(0.0f, (v.z - m) * r * gv.z + bv.z);
    o[3] = fmaxf(0.0f, (v.w - m) * r * gv.w + bv.w);
    long base = (long)row * 1024 + tid * 4;
    #pragma unroll
    for (int j = 0; j < 4; j++) {
        __nv_bfloat16 h = __float2bfloat16(o[j]);
        Xh[base + j] = h;
        Xl[base + j] = __float2bfloat16(o[j] - __bfloat162float(h));
    }
}

// ---------------- sampling: 1 warp per batch row --------------------------------
__global__ void sample_k(const float* __restrict__ Yh, const int* __restrict__ mask,
                         const float* __restrict__ gum, float* __restrict__ out)
{
    const int warp = threadIdx.x >> 5;
    const int lane = threadIdx.x & 31;
    const int b    = blockIdx.x * 4 + warp;
    const float* lr = Yh + (long)b * 128;

    for (int a = lane; a < 94; a += 32)
        out[OFF_LOGITS + (long)b * 94 + a] = lr[a];
    if (lane == 0)
        out[OFF_VAL + b] = lr[94];

    int a_prev = -1;
    #pragma unroll
    for (int j = 0; j < 2; j++) {
        int mk[2];
        #pragma unroll
        for (int t = 0; t < 2; t++) {
            int a = lane + 32 * t;
            int m = 0;
            if (a < 47) {
                m = mask[(long)b * 94 + j * 47 + a];
                if (j == 1) {
                    if (a_prev >= 1 && a_prev <= 6 && a == a_prev) m = 0;
                    if (a_prev > 26 && a_prev <= 46 && a >= 27)    m = 0;
                    if (a_prev == 0 && a == 0)                     m = 0;
                }
            }
            mk[t] = m;
        }
        if (j == 1) {
            int ssum = mk[0] + mk[1];
            #pragma unroll
            for (int off = 16; off; off >>= 1)
                ssum += __shfl_xor_sync(0xffffffffu, ssum, off);
            if (ssum == 0 && a_prev == 0 && lane == 0) mk[0] = 1;
        }

        float lv[2], key[2];
        #pragma unroll
        for (int t = 0; t < 2; t++) {
            int a = lane + 32 * t;
            if (a < 47) {
                float lg = lr[j * 47 + a];
                lv[t]  = mk[t] ? lg : NEGV;
                key[t] = lv[t] + gum[(long)b * 94 + j * 47 + a];
            } else {
                lv[t]  = -FLT_MAXV;
                key[t] = -FLT_MAXV;
            }
        }

        float bk = key[0]; int bi = lane;
        if (key[1] > bk) { bk = key[1]; bi = lane + 32; }
        #pragma unroll
        for (int off = 16; off; off >>= 1) {
            float ok = __shfl_xor_sync(0xffffffffu, bk, off);
            int   oi = __shfl_xor_sync(0xffffffffu, bi, off);
            if (ok > bk || (ok == bk && oi < bi)) { bk = ok; bi = oi; }
        }

        float mx = fmaxf(lv[0], lv[1]);
        #pragma unroll
        for (int off = 16; off; off >>= 1)
            mx = fmaxf(mx, __shfl_xor_sync(0xffffffffu, mx, off));
        float es = 0.0f;
        if (lane      < 47) es += expf(lv[0] - mx);
        if (lane + 32 < 47) es += expf(lv[1] - mx);
        #pragma unroll
        for (int off = 16; off; off >>= 1)
            es += __shfl_xor_sync(0xffffffffu, es, off);

        float lsel = __shfl_sync(0xffffffffu, lv[bi >= 32 ? 1 : 0], bi & 31);
        float logp = lsel - mx - logf(es);

        if (lane == 0) {
            out[OFF_LP  + (long)b * 2 + j] = logp;
            out[OFF_ACT + (long)b * 2 + j] = (float)bi;
        }
        a_prev = bi;
    }
}

// ---------------- launcher ----------------
extern "C" void kernel_launch(void* const* d_in, const int* in_sizes, int n_in,
                              void* d_out, int out_size)
{
    const float* obs  = (const float*)d_in[0];
    const int*   am   = (const int*)  d_in[1];
    const float* gum  = (const float*)d_in[2];
    const float* W0   = (const float*)d_in[3];
    const float* b0   = (const float*)d_in[4];
    const float* g0   = (const float*)d_in[5];
    const float* be0  = (const float*)d_in[6];
    const float* W1   = (const float*)d_in[7];
    const float* b1   = (const float*)d_in[8];
    const float* g1   = (const float*)d_in[9];
    const float* be1  = (const float*)d_in[10];
    const float* W2   = (const float*)d_in[11];
    const float* b2   = (const float*)d_in[12];
    const float* g2   = (const float*)d_in[13];
    const float* be2  = (const float*)d_in[14];
    const float* Wp   = (const float*)d_in[15];
    const float* bp   = (const float*)d_in[16];
    const float* Wv   = (const float*)d_in[17];
    const float* bv   = (const float*)d_in[18];
    float* out = (float*)d_out;

    __nv_bfloat16 *A0h, *A0l, *B0h, *B0l, *B1h, *B1l, *B2h, *B2l, *Bhh, *Bhl, *Xh, *Xl;
    float *bh, *Y, *Yh;
    cudaGetSymbolAddress((void**)&A0h, g_A0h);
    cudaGetSymbolAddress((void**)&A0l, g_A0l);
    cudaGetSymbolAddress((void**)&B0h, g_B0h);
    cudaGetSymbolAddress((void**)&B0l, g_B0l);
    cudaGetSymbolAddress((void**)&B1h, g_B1h);
    cudaGetSymbolAddress((void**)&B1l, g_B1l);
    cudaGetSymbolAddress((void**)&B2h, g_B2h);
    cudaGetSymbolAddress((void**)&B2l, g_B2l);
    cudaGetSymbolAddress((void**)&Bhh, g_Bhh);
    cudaGetSymbolAddress((void**)&Bhl, g_Bhl);
    cudaGetSymbolAddress((void**)&bh,  g_bh);
    cudaGetSymbolAddress((void**)&Y,   g_Y);
    cudaGetSymbolAddress((void**)&Xh,  g_Xh);
    cudaGetSymbolAddress((void**)&Xl,  g_Xl);
    cudaGetSymbolAddress((void**)&Yh,  g_Yh);

    const int SMEM_GEMM = 3 * 32768;   // 96 KB
    cudaFuncSetAttribute(gemm_hmma, cudaFuncAttributeMaxDynamicSharedMemorySize, SMEM_GEMM);

    // --- conversions / packing ---
    {
        long n = 4096L * 7168;
        split_obs_k<<<(unsigned)((n + 255) / 256), 256>>>(obs);
    }
    transpose_split_k<<<dim3(7168 / 32, 1024 / 32), dim3(32, 8)>>>(W0, B0h, B0l, 7150, 7168, 1024);
    transpose_split_k<<<dim3(1024 / 32, 1024 / 32), dim3(32, 8)>>>(W1, B1h, B1l, 1024, 1024, 1024);
    transpose_split_k<<<dim3(1024 / 32, 1024 / 32), dim3(32, 8)>>>(W2, B2h, B2l, 1024, 1024, 1024);
    pack_head_k<<<(128 * 1024 + 255) / 256, 256>>>(Wp, bp, Wv, bv);

    dim3 grid0(1024 / 128, 4096 / 128);   // (8, 32)

    // layer 0
    gemm_hmma<<<grid0, 256, SMEM_GEMM>>>(A0h, A0l, B0h, B0l, b0, Y, 1024, 7168);
    ln_relu_split_k<<<4096, 256>>>(Y, g0, be0, Xh, Xl);
    // layer 1
    gemm_hmma<<<grid0, 256, SMEM_GEMM>>>(Xh, Xl, B1h, B1l, b1, Y, 1024, 1024);
    ln_relu_split_k<<<4096, 256>>>(Y, g1, be1, Xh, Xl);
    // layer 2
    gemm_hmma<<<grid0, 256, SMEM_GEMM>>>(Xh, Xl, B2h, B2l, b2, Y, 1024, 1024);
    ln_relu_split_k<<<4096, 256>>>(Y, g2, be2, Xh, Xl);

    // heads: N=128 (cols 0..93 policy, 94 value)
    gemm_hmma<<<dim3(1, 4096 / 128), 256, SMEM_GEMM>>>(Xh, Xl, Bhh, Bhl, bh, Yh, 128, 1024);

    // sampling + output packing
    sample_k<<<4096 / 4, 128>>>(Yh, am, gum, out);
}